// round 10
// baseline (speedup 1.0000x reference)
#include <cuda_runtime.h>
#include <cuda_fp16.h>
#include <cstdint>

#define T_DIM 8192
#define D_DIM 4096
#define E_DIM 64

// ===========================================================================
// Fused router kernel: GEMM (legacy mma.sync m16n8k16 fp16, scaled fp16x2
// split) + softmax + JAX-partitionable-threefry Gumbel top-k, one kernel.
//
// Split: hi = f16(x), lo = f16((x-hi)*2048); logits = hi*hi + (hi*lo+lo*hi)/2048.
// Grid: 128 CTAs, one 64-row M-tile each, full K=4096. 256 threads.
// Warp w: rows (w&3)*16..+15, experts (w>>2)*32..+31 (4 n-tiles).
// Per 16-K step: 6 ldmatrix.x4 + 12 MMAs. 3072 MMAs/warp total (= R9).
// Double-buffered smem; after the mainloop the CTA's full 64x64 logits are
// staged in smem and the epilogue (softmax/Gumbel/rank top-k) runs in-place.
// ===========================================================================

constexpr int BKC     = 64;
constexpr int NCHUNK  = D_DIM / BKC;      // 64
constexpr int PITCH   = 144;              // bytes per f16 row (128 data + 16 pad)
constexpr int A_PLANE = 64 * PITCH;       // 9216
constexpr int B_PLANE = 64 * PITCH;       // 9216
constexpr int SB_OFF  = 2 * A_PLANE;      // 18432
constexpr int BUF     = 2 * A_PLANE + 2 * B_PLANE;  // 36864
constexpr int SMEM_BYTES = 2 * BUF;                  // 73728
constexpr int LS_STRIDE  = 68;            // logits smem row stride (floats)
constexpr int SS_OFF     = 64 * LS_STRIDE * 4;       // 17408 (after ls)
constexpr float LO_SCALE   = 2048.0f;
constexpr float LO_UNSCALE = 1.0f / 2048.0f;

__device__ __forceinline__ uint32_t smem_to_u32(const void* p) {
    uint32_t a;
    asm("{ .reg .u64 t; cvta.to.shared.u64 t, %1; cvt.u32.u64 %0, t; }"
        : "=r"(a) : "l"(p));
    return a;
}

#define LDSM4(r, addr) \
    asm volatile("ldmatrix.sync.aligned.m8n8.x4.shared.b16 {%0,%1,%2,%3}, [%4];" \
                 : "=r"((r)[0]), "=r"((r)[1]), "=r"((r)[2]), "=r"((r)[3])        \
                 : "r"(addr))

#define MMA16816(acc, A, Bp) \
    asm volatile("mma.sync.aligned.m16n8k16.row.col.f32.f16.f16.f32 "            \
                 "{%0,%1,%2,%3}, {%4,%5,%6,%7}, {%8,%9}, {%0,%1,%2,%3};"         \
                 : "+f"((acc)[0]), "+f"((acc)[1]), "+f"((acc)[2]), "+f"((acc)[3])\
                 : "r"((A)[0]), "r"((A)[1]), "r"((A)[2]), "r"((A)[3]),           \
                   "r"((Bp)[0]), "r"((Bp)[1]))

__device__ __forceinline__ void cvt4h(float4 v, uint2& hi, uint2& lo) {
    __half2 h0 = __floats2half2_rn(v.x, v.y);
    __half2 h1 = __floats2half2_rn(v.z, v.w);
    float2 f0 = __half22float2(h0), f1 = __half22float2(h1);
    __half2 l0 = __floats2half2_rn((v.x - f0.x) * LO_SCALE, (v.y - f0.y) * LO_SCALE);
    __half2 l1 = __floats2half2_rn((v.z - f1.x) * LO_SCALE, (v.w - f1.y) * LO_SCALE);
    hi = make_uint2(*reinterpret_cast<uint32_t*>(&h0), *reinterpret_cast<uint32_t*>(&h1));
    lo = make_uint2(*reinterpret_cast<uint32_t*>(&l0), *reinterpret_cast<uint32_t*>(&l1));
}

// ---- JAX partitionable threefry: bits[i] = x0^x1 of threefry2x32((0,42),(0,i))
__device__ __forceinline__ uint32_t rotl32(uint32_t x, int r) {
    return (x << r) | (x >> (32 - r));
}
__device__ __forceinline__ uint32_t threefry_xor_42(uint32_t c1) {
    const uint32_t ks0 = 0u, ks1 = 42u;
    const uint32_t ks2 = 0x1BD11BDAu ^ ks0 ^ ks1;
    uint32_t x0 = 0u + ks0, x1 = c1 + ks1;
#define TF_R(r) { x0 += x1; x1 = rotl32(x1, (r)); x1 ^= x0; }
    TF_R(13) TF_R(15) TF_R(26) TF_R(6)   x0 += ks1; x1 += ks2 + 1u;
    TF_R(17) TF_R(29) TF_R(16) TF_R(24)  x0 += ks2; x1 += ks0 + 2u;
    TF_R(13) TF_R(15) TF_R(26) TF_R(6)   x0 += ks0; x1 += ks1 + 3u;
    TF_R(17) TF_R(29) TF_R(16) TF_R(24)  x0 += ks1; x1 += ks2 + 4u;
    TF_R(13) TF_R(15) TF_R(26) TF_R(6)   x0 += ks2; x1 += ks0 + 5u;
#undef TF_R
    return x0 ^ x1;
}
__device__ __forceinline__ float gumbel_from_bits(uint32_t bits) {
    float f = __uint_as_float((bits >> 9) | 0x3F800000u) - 1.0f;
    const float lo = 1e-6f;
    const float hi = (float)(1.0 - 1e-6);
    float u = fmaxf(lo, __fadd_rn(__fmul_rn(f, __fsub_rn(hi, lo)), lo));
    return -logf(-logf(u));
}

__global__ __launch_bounds__(256, 1) void router_kernel(
    const float* __restrict__ H, const float* __restrict__ Wm,
    const float* __restrict__ bias, const int* __restrict__ kptr,
    float* __restrict__ mask_out, float* __restrict__ wout,
    float* __restrict__ logits_out)
{
    extern __shared__ __align__(16) char smem[];
    const uint32_t sbase = smem_to_u32(smem);
    const int tid  = threadIdx.x;
    const int warp = tid >> 5;
    const int lane = tid & 31;
    const int row0 = blockIdx.x * 64;
    const int mrow = (warp & 3) * 16;
    const int ncol = (warp >> 2) * 32;

    float accM[4][4], accC[4][4];
#pragma unroll
    for (int n = 0; n < 4; n++)
#pragma unroll
        for (int j = 0; j < 4; j++) { accM[n][j] = 0.f; accC[n][j] = 0.f; }

    const uint32_t aBase = sbase
        + (uint32_t)((mrow + (lane & 15)) * PITCH + ((lane >> 4) << 4));
    const uint32_t bBase = sbase + SB_OFF
        + (uint32_t)((ncol + ((lane & 7) | ((lane >> 4) << 3))) * PITCH
                     + (((lane >> 3) & 1) << 4));

    const int seg = tid & 15;
    const int rA  = tid >> 4;                      // + 16*i, i<4
    const uint32_t stsOff = (uint32_t)(seg * 8);

    float4 pa[4], pb[4];
#pragma unroll
    for (int i = 0; i < 4; i++) {
        pa[i] = *(const float4*)(H + (size_t)(row0 + rA + 16 * i) * D_DIM + seg * 4);
        pb[i] = *(const float4*)(Wm + (size_t)(rA + 16 * i) * D_DIM + seg * 4);
    }

    // Prologue: fill buffer 0 with chunk 0.
#pragma unroll
    for (int i = 0; i < 4; i++) {
        uint2 h, l;
        const uint32_t ro = (uint32_t)((rA + 16 * i) * PITCH) + stsOff;
        cvt4h(pa[i], h, l);
        *(uint2*)(smem + 0 * A_PLANE + ro) = h;
        *(uint2*)(smem + 1 * A_PLANE + ro) = l;
        cvt4h(pb[i], h, l);
        *(uint2*)(smem + SB_OFF + 0 * B_PLANE + ro) = h;
        *(uint2*)(smem + SB_OFF + 1 * B_PLANE + ro) = l;
    }
    __syncthreads();

    for (int c = 0; c < NCHUNK; c++) {
        const uint32_t bufR = (uint32_t)((c & 1) * BUF);
        const uint32_t bufW = (uint32_t)(((c + 1) & 1) * BUF);

        if (c + 1 < NCHUNK) {   // issue LDG early; consumed after the MMA sweep
            const int kb = (c + 1) * BKC;
#pragma unroll
            for (int i = 0; i < 4; i++) {
                pa[i] = *(const float4*)(H + (size_t)(row0 + rA + 16 * i) * D_DIM + kb + seg * 4);
                pb[i] = *(const float4*)(Wm + (size_t)(rA + 16 * i) * D_DIM + kb + seg * 4);
            }
        }

#pragma unroll
        for (int s = 0; s < 4; s++) {
            const uint32_t ks = (uint32_t)(s * 32);
            uint32_t Ah[4], Al[4];
            LDSM4(Ah, aBase + bufR + 0 * A_PLANE + ks);
            LDSM4(Al, aBase + bufR + 1 * A_PLANE + ks);
            uint32_t Bh[8], Bl[8];
#pragma unroll
            for (int np = 0; np < 2; np++) {
                const uint32_t bo = bBase + bufR + (uint32_t)(np * 16 * PITCH) + ks;
                LDSM4(&Bh[np * 4], bo + 0 * B_PLANE);
                LDSM4(&Bl[np * 4], bo + 1 * B_PLANE);
            }
#pragma unroll
            for (int n = 0; n < 4; n++) MMA16816(accM[n], Ah, &Bh[n * 2]);
#pragma unroll
            for (int n = 0; n < 4; n++) MMA16816(accC[n], Ah, &Bl[n * 2]);
#pragma unroll
            for (int n = 0; n < 4; n++) MMA16816(accC[n], Al, &Bh[n * 2]);
        }

        if (c + 1 < NCHUNK) {
#pragma unroll
            for (int i = 0; i < 4; i++) {
                uint2 h, l;
                const uint32_t ro = (uint32_t)((rA + 16 * i) * PITCH) + stsOff;
                cvt4h(pa[i], h, l);
                *(uint2*)(smem + bufW + 0 * A_PLANE + ro) = h;
                *(uint2*)(smem + bufW + 1 * A_PLANE + ro) = l;
                cvt4h(pb[i], h, l);
                *(uint2*)(smem + bufW + SB_OFF + 0 * B_PLANE + ro) = h;
                *(uint2*)(smem + bufW + SB_OFF + 1 * B_PLANE + ro) = l;
            }
        }
        __syncthreads();
    }

    // ---- Stage logits (no bias yet) into smem ls[64][68] (overlays buffer 0).
    float* ls = (float*)smem;
    {
        const int g  = lane >> 2;
        const int t2 = (lane & 3) * 2;
#pragma unroll
        for (int n = 0; n < 4; n++) {
            const int col = ncol + n * 8 + t2;
            ls[(mrow + g)     * LS_STRIDE + col]     = fmaf(accC[n][0], LO_UNSCALE, accM[n][0]);
            ls[(mrow + g)     * LS_STRIDE + col + 1] = fmaf(accC[n][1], LO_UNSCALE, accM[n][1]);
            ls[(mrow + g + 8) * LS_STRIDE + col]     = fmaf(accC[n][2], LO_UNSCALE, accM[n][2]);
            ls[(mrow + g + 8) * LS_STRIDE + col + 1] = fmaf(accC[n][3], LO_UNSCALE, accM[n][3]);
        }
    }
    __syncthreads();

    // ---- Fused epilogue: warp w handles local rows w*8 .. w*8+7.
    float* ss = (float*)(smem + SS_OFF);   // [8][64] per-warp scratch
    const int k  = *kptr;
    const int e0 = lane, e1 = lane + 32;
    const float be0 = bias[e0], be1 = bias[e1];

    for (int r8 = 0; r8 < 8; r8++) {
        const int r    = warp * 8 + r8;
        const int grow = row0 + r;
        const size_t base = (size_t)grow * E_DIM;

        float l0 = ls[r * LS_STRIDE + e0] + be0;
        float l1 = ls[r * LS_STRIDE + e1] + be1;

        const uint32_t i0 = (uint32_t)(grow * E_DIM) + (uint32_t)e0;
        float s0 = l0 + gumbel_from_bits(threefry_xor_42(i0));
        float s1 = l1 + gumbel_from_bits(threefry_xor_42(i0 + 32u));

        float m = fmaxf(l0, l1);
#pragma unroll
        for (int off = 16; off; off >>= 1)
            m = fmaxf(m, __shfl_xor_sync(0xffffffffu, m, off));
        float p0 = expf(l0 - m), p1 = expf(l1 - m);
        float sum = p0 + p1;
#pragma unroll
        for (int off = 16; off; off >>= 1)
            sum += __shfl_xor_sync(0xffffffffu, sum, off);

        ss[warp * 64 + e0] = s0;
        ss[warp * 64 + e1] = s1;
        __syncwarp();
        int c0 = 0, c1 = 0;
#pragma unroll
        for (int jj = 0; jj < 64; jj++) {
            float v = ss[warp * 64 + jj];
            c0 += (v > s0) || ((v == s0) && (jj < e0));
            c1 += (v > s1) || ((v == s1) && (jj < e1));
        }
        __syncwarp();

        mask_out[base + e0] = (c0 < k) ? 1.0f : 0.0f;
        mask_out[base + e1] = (c1 < k) ? 1.0f : 0.0f;
        wout[base + e0] = p0 / sum;
        wout[base + e1] = p1 / sum;
        logits_out[base + e0] = l0;
        logits_out[base + e1] = l1;
    }
}

// ===========================================================================
// Launch. Inputs matched by element count (h=33.5M, W=262144, bias=64, k=1).
// out = [mask | weight | logits], each T*E float32.
// ===========================================================================
extern "C" void kernel_launch(void* const* d_in, const int* in_sizes, int n_in,
                              void* d_out, int out_size) {
    const float* H    = nullptr;
    const float* Wm   = nullptr;
    const float* bias = nullptr;
    const int*   kptr = nullptr;
    for (int i = 0; i < n_in; i++) {
        long long sz = in_sizes[i];
        if (sz == (long long)T_DIM * D_DIM)      H    = (const float*)d_in[i];
        else if (sz == (long long)E_DIM * D_DIM) Wm   = (const float*)d_in[i];
        else if (sz == E_DIM)                    bias = (const float*)d_in[i];
        else if (sz == 1)                        kptr = (const int*)d_in[i];
    }
    if (!H)    H    = (const float*)d_in[0];
    if (!Wm)   Wm   = (const float*)d_in[1];
    if (!bias) bias = (const float*)d_in[2];
    if (!kptr) kptr = (const int*)d_in[3];

    float* out        = (float*)d_out;
    float* mask_out   = out;
    float* weight_out = out + (size_t)T_DIM * E_DIM;
    float* logits_out = out + 2 * (size_t)T_DIM * E_DIM;

    cudaFuncSetAttribute(router_kernel,
                         cudaFuncAttributeMaxDynamicSharedMemorySize, SMEM_BYTES);
    router_kernel<<<T_DIM / 64, 256, SMEM_BYTES>>>(
        H, Wm, bias, kptr, mask_out, weight_out, logits_out);
}

// round 11
// speedup vs baseline: 1.0845x; 1.0845x over previous
#include <cuda_runtime.h>
#include <cuda_fp16.h>
#include <cstdint>

#define T_DIM 8192
#define D_DIM 4096
#define E_DIM 64

// ===========================================================================
// Fused router kernel, 512 threads (16 warps = 4/SMSP for latency hiding).
// GEMM: legacy mma.sync m16n8k16 fp16, scaled fp16x2 split
//   hi = f16(x), lo = f16((x-hi)*2048); logits = hi*hi + (hi*lo + lo*hi)/2048.
// Grid: 128 CTAs, one 64-row M-tile each, full K = 4096.
// Warp w: rows (w&3)*16 .. +15, experts (w>>2)*16 .. +15.
// Per 16-K step: 4 ldmatrix.x4 + 6 MMAs into 3 independent acc groups.
// Epilogue (softmax + JAX partitionable-threefry Gumbel top-k) fused in-CTA.
// ===========================================================================

constexpr int BKC     = 64;
constexpr int NCHUNK  = D_DIM / BKC;      // 64
constexpr int PITCH   = 144;              // bytes per f16 row (128 data + 16 pad)
constexpr int A_PLANE = 64 * PITCH;       // 9216
constexpr int B_PLANE = 64 * PITCH;       // 9216
constexpr int SB_OFF  = 2 * A_PLANE;      // 18432
constexpr int BUF     = 2 * A_PLANE + 2 * B_PLANE;   // 36864
constexpr int SMEM_BYTES = 2 * BUF;                   // 73728
constexpr int LS_STRIDE  = 68;                        // logits smem row stride
constexpr int SS_OFF     = 64 * LS_STRIDE * 4;        // 17408
constexpr float LO_SCALE   = 2048.0f;
constexpr float LO_UNSCALE = 1.0f / 2048.0f;

__device__ __forceinline__ uint32_t smem_to_u32(const void* p) {
    uint32_t a;
    asm("{ .reg .u64 t; cvta.to.shared.u64 t, %1; cvt.u32.u64 %0, t; }"
        : "=r"(a) : "l"(p));
    return a;
}

#define LDSM4(r, addr) \
    asm volatile("ldmatrix.sync.aligned.m8n8.x4.shared.b16 {%0,%1,%2,%3}, [%4];" \
                 : "=r"((r)[0]), "=r"((r)[1]), "=r"((r)[2]), "=r"((r)[3])        \
                 : "r"(addr))

#define MMA16816(acc, A, Bp) \
    asm volatile("mma.sync.aligned.m16n8k16.row.col.f32.f16.f16.f32 "            \
                 "{%0,%1,%2,%3}, {%4,%5,%6,%7}, {%8,%9}, {%0,%1,%2,%3};"         \
                 : "+f"((acc)[0]), "+f"((acc)[1]), "+f"((acc)[2]), "+f"((acc)[3])\
                 : "r"((A)[0]), "r"((A)[1]), "r"((A)[2]), "r"((A)[3]),           \
                   "r"((Bp)[0]), "r"((Bp)[1]))

__device__ __forceinline__ void cvt4h(float4 v, uint2& hi, uint2& lo) {
    __half2 h0 = __floats2half2_rn(v.x, v.y);
    __half2 h1 = __floats2half2_rn(v.z, v.w);
    float2 f0 = __half22float2(h0), f1 = __half22float2(h1);
    __half2 l0 = __floats2half2_rn((v.x - f0.x) * LO_SCALE, (v.y - f0.y) * LO_SCALE);
    __half2 l1 = __floats2half2_rn((v.z - f1.x) * LO_SCALE, (v.w - f1.y) * LO_SCALE);
    hi = make_uint2(*reinterpret_cast<uint32_t*>(&h0), *reinterpret_cast<uint32_t*>(&h1));
    lo = make_uint2(*reinterpret_cast<uint32_t*>(&l0), *reinterpret_cast<uint32_t*>(&l1));
}

// ---- JAX partitionable threefry: bits[i] = x0^x1 of threefry2x32((0,42),(0,i))
__device__ __forceinline__ uint32_t rotl32(uint32_t x, int r) {
    return (x << r) | (x >> (32 - r));
}
__device__ __forceinline__ uint32_t threefry_xor_42(uint32_t c1) {
    const uint32_t ks0 = 0u, ks1 = 42u;
    const uint32_t ks2 = 0x1BD11BDAu ^ ks0 ^ ks1;
    uint32_t x0 = 0u + ks0, x1 = c1 + ks1;
#define TF_R(r) { x0 += x1; x1 = rotl32(x1, (r)); x1 ^= x0; }
    TF_R(13) TF_R(15) TF_R(26) TF_R(6)   x0 += ks1; x1 += ks2 + 1u;
    TF_R(17) TF_R(29) TF_R(16) TF_R(24)  x0 += ks2; x1 += ks0 + 2u;
    TF_R(13) TF_R(15) TF_R(26) TF_R(6)   x0 += ks0; x1 += ks1 + 3u;
    TF_R(17) TF_R(29) TF_R(16) TF_R(24)  x0 += ks1; x1 += ks2 + 4u;
    TF_R(13) TF_R(15) TF_R(26) TF_R(6)   x0 += ks2; x1 += ks0 + 5u;
#undef TF_R
    return x0 ^ x1;
}
__device__ __forceinline__ float gumbel_from_bits(uint32_t bits) {
    float f = __uint_as_float((bits >> 9) | 0x3F800000u) - 1.0f;
    const float lo = 1e-6f;
    const float hi = (float)(1.0 - 1e-6);
    float u = fmaxf(lo, __fadd_rn(__fmul_rn(f, __fsub_rn(hi, lo)), lo));
    return -logf(-logf(u));
}

__global__ __launch_bounds__(512, 1) void router_kernel(
    const float* __restrict__ H, const float* __restrict__ Wm,
    const float* __restrict__ bias, const int* __restrict__ kptr,
    float* __restrict__ mask_out, float* __restrict__ wout,
    float* __restrict__ logits_out)
{
    extern __shared__ __align__(16) char smem[];
    const uint32_t sbase = smem_to_u32(smem);
    const int tid  = threadIdx.x;
    const int warp = tid >> 5;
    const int lane = tid & 31;
    const int row0 = blockIdx.x * 64;
    const int mrow = (warp & 3) * 16;
    const int ncol = (warp >> 2) * 16;

    float accM[2][4], accC1[2][4], accC2[2][4];
#pragma unroll
    for (int n = 0; n < 2; n++)
#pragma unroll
        for (int j = 0; j < 4; j++) {
            accM[n][j] = 0.f; accC1[n][j] = 0.f; accC2[n][j] = 0.f;
        }

    const uint32_t aBase = sbase
        + (uint32_t)((mrow + (lane & 15)) * PITCH + ((lane >> 4) << 4));
    const uint32_t bBase = sbase + SB_OFF
        + (uint32_t)((ncol + ((lane & 7) | ((lane >> 4) << 3))) * PITCH
                     + (((lane >> 3) & 1) << 4));

    // LDG geometry: seg = tid&15 (16B segment), rA = tid>>4 in 0..31.
    const int seg = tid & 15;
    const int rA  = tid >> 4;                       // + 32*i
    const uint32_t stsOff = (uint32_t)(seg * 8);

    float4 pa[2], pb[2];
#pragma unroll
    for (int i = 0; i < 2; i++) {
        pa[i] = *(const float4*)(H + (size_t)(row0 + rA + 32 * i) * D_DIM + seg * 4);
        pb[i] = *(const float4*)(Wm + (size_t)(rA + 32 * i) * D_DIM + seg * 4);
    }

    // Prologue: fill buffer 0 with chunk 0.
#pragma unroll
    for (int i = 0; i < 2; i++) {
        uint2 h, l;
        const uint32_t ro = (uint32_t)((rA + 32 * i) * PITCH) + stsOff;
        cvt4h(pa[i], h, l);
        *(uint2*)(smem + 0 * A_PLANE + ro) = h;
        *(uint2*)(smem + 1 * A_PLANE + ro) = l;
        cvt4h(pb[i], h, l);
        *(uint2*)(smem + SB_OFF + 0 * B_PLANE + ro) = h;
        *(uint2*)(smem + SB_OFF + 1 * B_PLANE + ro) = l;
    }
    __syncthreads();

    for (int c = 0; c < NCHUNK; c++) {
        const uint32_t bufR = (uint32_t)((c & 1) * BUF);
        const uint32_t bufW = (uint32_t)(((c + 1) & 1) * BUF);

        if (c + 1 < NCHUNK) {   // issue LDG early; consumed after the MMA sweep
            const int kb = (c + 1) * BKC;
#pragma unroll
            for (int i = 0; i < 2; i++) {
                pa[i] = *(const float4*)(H + (size_t)(row0 + rA + 32 * i) * D_DIM + kb + seg * 4);
                pb[i] = *(const float4*)(Wm + (size_t)(rA + 32 * i) * D_DIM + kb + seg * 4);
            }
        }

#pragma unroll
        for (int s = 0; s < 4; s++) {
            const uint32_t ks = (uint32_t)(s * 32);
            uint32_t Ah[4], Al[4], Bh[4], Bl[4];
            LDSM4(Ah, aBase + bufR + 0 * A_PLANE + ks);
            LDSM4(Al, aBase + bufR + 1 * A_PLANE + ks);
            LDSM4(Bh, bBase + bufR + 0 * B_PLANE + ks);
            LDSM4(Bl, bBase + bufR + 1 * B_PLANE + ks);
            // 6 MMAs, 3 independent acc groups -> RAW distance 6.
            MMA16816(accM[0],  Ah, &Bh[0]);
            MMA16816(accM[1],  Ah, &Bh[2]);
            MMA16816(accC1[0], Ah, &Bl[0]);
            MMA16816(accC1[1], Ah, &Bl[2]);
            MMA16816(accC2[0], Al, &Bh[0]);
            MMA16816(accC2[1], Al, &Bh[2]);
        }

        if (c + 1 < NCHUNK) {
#pragma unroll
            for (int i = 0; i < 2; i++) {
                uint2 h, l;
                const uint32_t ro = (uint32_t)((rA + 32 * i) * PITCH) + stsOff;
                cvt4h(pa[i], h, l);
                *(uint2*)(smem + bufW + 0 * A_PLANE + ro) = h;
                *(uint2*)(smem + bufW + 1 * A_PLANE + ro) = l;
                cvt4h(pb[i], h, l);
                *(uint2*)(smem + bufW + SB_OFF + 0 * B_PLANE + ro) = h;
                *(uint2*)(smem + bufW + SB_OFF + 1 * B_PLANE + ro) = l;
            }
        }
        __syncthreads();
    }

    // ---- Stage logits (no bias yet) into smem ls[64][68] (overlays buffer 0).
    float* ls = (float*)smem;
    {
        const int g  = lane >> 2;
        const int t2 = (lane & 3) * 2;
#pragma unroll
        for (int n = 0; n < 2; n++) {
            const int col = ncol + n * 8 + t2;
#pragma unroll
            for (int j = 0; j < 2; j++) {   // j=0 -> regs {0,1} row g; j=1 -> {2,3} row g+8
                float c0 = accC1[n][2 * j]     + accC2[n][2 * j];
                float c1 = accC1[n][2 * j + 1] + accC2[n][2 * j + 1];
                ls[(mrow + g + 8 * j) * LS_STRIDE + col]     = fmaf(c0, LO_UNSCALE, accM[n][2 * j]);
                ls[(mrow + g + 8 * j) * LS_STRIDE + col + 1] = fmaf(c1, LO_UNSCALE, accM[n][2 * j + 1]);
            }
        }
    }
    __syncthreads();

    // ---- Fused epilogue: warp w handles local rows w*4 .. w*4+3.
    float* ss = (float*)(smem + SS_OFF);   // [16][64] per-warp scratch
    const int k  = *kptr;
    const int e0 = lane, e1 = lane + 32;
    const float be0 = bias[e0], be1 = bias[e1];

#pragma unroll
    for (int r4 = 0; r4 < 4; r4++) {
        const int r    = warp * 4 + r4;
        const int grow = row0 + r;
        const size_t base = (size_t)grow * E_DIM;

        float l0 = ls[r * LS_STRIDE + e0] + be0;
        float l1 = ls[r * LS_STRIDE + e1] + be1;

        const uint32_t i0 = (uint32_t)(grow * E_DIM) + (uint32_t)e0;
        float s0 = l0 + gumbel_from_bits(threefry_xor_42(i0));
        float s1 = l1 + gumbel_from_bits(threefry_xor_42(i0 + 32u));

        float m = fmaxf(l0, l1);
#pragma unroll
        for (int off = 16; off; off >>= 1)
            m = fmaxf(m, __shfl_xor_sync(0xffffffffu, m, off));
        float p0 = expf(l0 - m), p1 = expf(l1 - m);
        float sum = p0 + p1;
#pragma unroll
        for (int off = 16; off; off >>= 1)
            sum += __shfl_xor_sync(0xffffffffu, sum, off);

        ss[warp * 64 + e0] = s0;
        ss[warp * 64 + e1] = s1;
        __syncwarp();
        int c0 = 0, c1 = 0;
#pragma unroll
        for (int jj = 0; jj < 64; jj++) {
            float v = ss[warp * 64 + jj];
            c0 += (v > s0) || ((v == s0) && (jj < e0));
            c1 += (v > s1) || ((v == s1) && (jj < e1));
        }
        __syncwarp();

        mask_out[base + e0] = (c0 < k) ? 1.0f : 0.0f;
        mask_out[base + e1] = (c1 < k) ? 1.0f : 0.0f;
        wout[base + e0] = p0 / sum;
        wout[base + e1] = p1 / sum;
        logits_out[base + e0] = l0;
        logits_out[base + e1] = l1;
    }
}

// ===========================================================================
// Launch. Inputs matched by element count (h=33.5M, W=262144, bias=64, k=1).
// out = [mask | weight | logits], each T*E float32.
// ===========================================================================
extern "C" void kernel_launch(void* const* d_in, const int* in_sizes, int n_in,
                              void* d_out, int out_size) {
    const float* H    = nullptr;
    const float* Wm   = nullptr;
    const float* bias = nullptr;
    const int*   kptr = nullptr;
    for (int i = 0; i < n_in; i++) {
        long long sz = in_sizes[i];
        if (sz == (long long)T_DIM * D_DIM)      H    = (const float*)d_in[i];
        else if (sz == (long long)E_DIM * D_DIM) Wm   = (const float*)d_in[i];
        else if (sz == E_DIM)                    bias = (const float*)d_in[i];
        else if (sz == 1)                        kptr = (const int*)d_in[i];
    }
    if (!H)    H    = (const float*)d_in[0];
    if (!Wm)   Wm   = (const float*)d_in[1];
    if (!bias) bias = (const float*)d_in[2];
    if (!kptr) kptr = (const int*)d_in[3];

    float* out        = (float*)d_out;
    float* mask_out   = out;
    float* weight_out = out + (size_t)T_DIM * E_DIM;
    float* logits_out = out + 2 * (size_t)T_DIM * E_DIM;

    cudaFuncSetAttribute(router_kernel,
                         cudaFuncAttributeMaxDynamicSharedMemorySize, SMEM_BYTES);
    router_kernel<<<T_DIM / 64, 512, SMEM_BYTES>>>(
        H, Wm, bias, kptr, mask_out, weight_out, logits_out);
}

// round 12
// speedup vs baseline: 1.4612x; 1.3474x over previous
#include <cuda_runtime.h>
#include <cuda_fp16.h>
#include <cstdint>

#define T_DIM 8192
#define D_DIM 4096
#define E_DIM 64

// ===========================================================================
// GEMM: legacy mma.sync m16n8k16 fp16, scaled fp16x2 split
//   hi = f16(x), lo = f16((x-hi)*2048); logits = hi*hi + (hi*lo + lo*hi)/2048.
// R9's proven per-warp tile (16 rows x 64 experts, 24-MMA runs) at DOUBLE the
// warp count: 512 threads / 16 warps (4 per SMSP), M-tile 256, KSPLIT 4.
// Grid: 32 m-tiles x 4 k-splits = 128 CTAs. BKC=32 keeps regs <= 128.
// ===========================================================================

constexpr int KSPLIT  = 4;
constexpr int KRANGE  = D_DIM / KSPLIT;   // 1024
constexpr int BKC     = 32;               // K per chunk
constexpr int NCHUNK  = KRANGE / BKC;     // 32
constexpr int PITCH   = 80;               // bytes per f16 row (64 data + 16 pad)
constexpr int A_PLANE = 256 * PITCH;      // 20480
constexpr int B_PLANE = 64 * PITCH;       // 5120
constexpr int SB_OFF  = 2 * A_PLANE;      // 40960
constexpr int BUF     = 2 * A_PLANE + 2 * B_PLANE;   // 51200
constexpr int SMEM_BYTES = 2 * BUF;                   // 102400
constexpr float LO_SCALE   = 2048.0f;
constexpr float LO_UNSCALE = 1.0f / 2048.0f;

__device__ float g_partial[KSPLIT][(size_t)T_DIM * E_DIM];   // 8 MB scratch

__device__ __forceinline__ uint32_t smem_to_u32(const void* p) {
    uint32_t a;
    asm("{ .reg .u64 t; cvta.to.shared.u64 t, %1; cvt.u32.u64 %0, t; }"
        : "=r"(a) : "l"(p));
    return a;
}

#define LDSM4(r, addr) \
    asm volatile("ldmatrix.sync.aligned.m8n8.x4.shared.b16 {%0,%1,%2,%3}, [%4];" \
                 : "=r"((r)[0]), "=r"((r)[1]), "=r"((r)[2]), "=r"((r)[3])        \
                 : "r"(addr))

#define MMA16816(acc, A, Bp) \
    asm volatile("mma.sync.aligned.m16n8k16.row.col.f32.f16.f16.f32 "            \
                 "{%0,%1,%2,%3}, {%4,%5,%6,%7}, {%8,%9}, {%0,%1,%2,%3};"         \
                 : "+f"((acc)[0]), "+f"((acc)[1]), "+f"((acc)[2]), "+f"((acc)[3])\
                 : "r"((A)[0]), "r"((A)[1]), "r"((A)[2]), "r"((A)[3]),           \
                   "r"((Bp)[0]), "r"((Bp)[1]))

__device__ __forceinline__ void cvt4h(float4 v, uint2& hi, uint2& lo) {
    __half2 h0 = __floats2half2_rn(v.x, v.y);
    __half2 h1 = __floats2half2_rn(v.z, v.w);
    float2 f0 = __half22float2(h0), f1 = __half22float2(h1);
    __half2 l0 = __floats2half2_rn((v.x - f0.x) * LO_SCALE, (v.y - f0.y) * LO_SCALE);
    __half2 l1 = __floats2half2_rn((v.z - f1.x) * LO_SCALE, (v.w - f1.y) * LO_SCALE);
    hi = make_uint2(*reinterpret_cast<uint32_t*>(&h0), *reinterpret_cast<uint32_t*>(&h1));
    lo = make_uint2(*reinterpret_cast<uint32_t*>(&l0), *reinterpret_cast<uint32_t*>(&l1));
}

__global__ __launch_bounds__(512, 1) void gemm_kernel(
    const float* __restrict__ H, const float* __restrict__ Wm)
{
    extern __shared__ __align__(16) char smem[];
    const uint32_t sbase = smem_to_u32(smem);
    const int tid  = threadIdx.x;
    const int warp = tid >> 5;
    const int lane = tid & 31;
    const int mtile = blockIdx.x >> 2;
    const int split = blockIdx.x & 3;
    const int row0  = mtile * 256;
    const int kb0   = split * KRANGE;
    const int mrow  = warp * 16;          // warp's rows within the 256-row tile

    float accM[8][4], accC[8][4];
#pragma unroll
    for (int n = 0; n < 8; n++)
#pragma unroll
        for (int j = 0; j < 4; j++) { accM[n][j] = 0.f; accC[n][j] = 0.f; }

    // ldmatrix bases (buffer 0; add (c&1)*BUF at use).
    const uint32_t aBase = sbase
        + (uint32_t)((mrow + (lane & 15)) * PITCH + ((lane >> 4) << 4));
    const uint32_t bBase = sbase + SB_OFF
        + (uint32_t)((((lane & 7) | ((lane >> 4) << 3)) * PITCH)
                     + (((lane >> 3) & 1) << 4));

    // LDG geometry: seg = tid&7 (16B segment of 32-K chunk), rA = tid>>3 (0..63).
    const int seg = tid & 7;
    const int rA  = tid >> 3;
    const uint32_t stsOff = (uint32_t)(seg * 8);   // 4 halves = 8 B

    float4 pa[4], pbv;
#pragma unroll
    for (int i = 0; i < 4; i++)
        pa[i] = *(const float4*)(H + (size_t)(row0 + rA + 64 * i) * D_DIM + kb0 + seg * 4);
    pbv = *(const float4*)(Wm + (size_t)rA * D_DIM + kb0 + seg * 4);

    // Prologue: fill buffer 0 with chunk 0.
#pragma unroll
    for (int i = 0; i < 4; i++) {
        uint2 h, l;
        const uint32_t ro = (uint32_t)((rA + 64 * i) * PITCH) + stsOff;
        cvt4h(pa[i], h, l);
        *(uint2*)(smem + 0 * A_PLANE + ro) = h;
        *(uint2*)(smem + 1 * A_PLANE + ro) = l;
    }
    {
        uint2 h, l;
        const uint32_t ro = (uint32_t)(rA * PITCH) + stsOff;
        cvt4h(pbv, h, l);
        *(uint2*)(smem + SB_OFF + 0 * B_PLANE + ro) = h;
        *(uint2*)(smem + SB_OFF + 1 * B_PLANE + ro) = l;
    }
    __syncthreads();

    for (int c = 0; c < NCHUNK; c++) {
        const uint32_t bufR = (uint32_t)((c & 1) * BUF);
        const uint32_t bufW = (uint32_t)(((c + 1) & 1) * BUF);

        if (c + 1 < NCHUNK) {   // issue LDG early; consumed after the MMA sweep
            const int kb = kb0 + (c + 1) * BKC;
#pragma unroll
            for (int i = 0; i < 4; i++)
                pa[i] = *(const float4*)(H + (size_t)(row0 + rA + 64 * i) * D_DIM + kb + seg * 4);
            pbv = *(const float4*)(Wm + (size_t)rA * D_DIM + kb + seg * 4);
        }

#pragma unroll
        for (int s = 0; s < 2; s++) {
            const uint32_t ks = (uint32_t)(s * 32);
            uint32_t Ah[4], Al[4];
            LDSM4(Ah, aBase + bufR + 0 * A_PLANE + ks);
            LDSM4(Al, aBase + bufR + 1 * A_PLANE + ks);
            // Two np-halves keep live B frags at 16 regs (fits 128-reg cap).
#pragma unroll
            for (int half = 0; half < 2; half++) {
                uint32_t Bh[8], Bl[8];
#pragma unroll
                for (int np = 0; np < 2; np++) {
                    const uint32_t bo = bBase + bufR
                        + (uint32_t)((half * 2 + np) * 16 * PITCH) + ks;
                    LDSM4(&Bh[np * 4], bo + 0 * B_PLANE);
                    LDSM4(&Bl[np * 4], bo + 1 * B_PLANE);
                }
                const int n0 = half * 4;
#pragma unroll
                for (int n = 0; n < 4; n++) MMA16816(accM[n0 + n],  Ah, &Bh[n * 2]);
#pragma unroll
                for (int n = 0; n < 4; n++) MMA16816(accC[n0 + n],  Ah, &Bl[n * 2]);
#pragma unroll
                for (int n = 0; n < 4; n++) MMA16816(accC[n0 + n],  Al, &Bh[n * 2]);
            }
        }

        if (c + 1 < NCHUNK) {   // convert + STS into the other buffer
#pragma unroll
            for (int i = 0; i < 4; i++) {
                uint2 h, l;
                const uint32_t ro = (uint32_t)((rA + 64 * i) * PITCH) + stsOff;
                cvt4h(pa[i], h, l);
                *(uint2*)(smem + bufW + 0 * A_PLANE + ro) = h;
                *(uint2*)(smem + bufW + 1 * A_PLANE + ro) = l;
            }
            {
                uint2 h, l;
                const uint32_t ro = (uint32_t)(rA * PITCH) + stsOff;
                cvt4h(pbv, h, l);
                *(uint2*)(smem + bufW + SB_OFF + 0 * B_PLANE + ro) = h;
                *(uint2*)(smem + bufW + SB_OFF + 1 * B_PLANE + ro) = l;
            }
        }
        __syncthreads();
    }

    // Write partials: value = accM + accC/2048. C-frag: reg j -> (row g(+8), col 2t(+1)).
    const int g  = lane >> 2;
    const int t2 = (lane & 3) * 2;
    const int rowA = row0 + mrow + g;
#pragma unroll
    for (int n = 0; n < 8; n++) {
        float v0 = fmaf(accC[n][0], LO_UNSCALE, accM[n][0]);
        float v1 = fmaf(accC[n][1], LO_UNSCALE, accM[n][1]);
        float v2 = fmaf(accC[n][2], LO_UNSCALE, accM[n][2]);
        float v3 = fmaf(accC[n][3], LO_UNSCALE, accM[n][3]);
        *(float2*)&g_partial[split][(size_t)rowA * E_DIM + n * 8 + t2]       = make_float2(v0, v1);
        *(float2*)&g_partial[split][(size_t)(rowA + 8) * E_DIM + n * 8 + t2] = make_float2(v2, v3);
    }
}

// ===========================================================================
// Epilogue: logits = sum of 4 K-split partials + bias; JAX partitionable
// threefry Gumbel (bits = x0^x1), softmax(clean logits), rank top-k mask.
// ===========================================================================

__device__ __forceinline__ uint32_t rotl32(uint32_t x, int r) {
    return (x << r) | (x >> (32 - r));
}
__device__ __forceinline__ uint32_t threefry_xor_42(uint32_t c1) {
    const uint32_t ks0 = 0u, ks1 = 42u;
    const uint32_t ks2 = 0x1BD11BDAu ^ ks0 ^ ks1;
    uint32_t x0 = 0u + ks0, x1 = c1 + ks1;
#define TF_R(r) { x0 += x1; x1 = rotl32(x1, (r)); x1 ^= x0; }
    TF_R(13) TF_R(15) TF_R(26) TF_R(6)   x0 += ks1; x1 += ks2 + 1u;
    TF_R(17) TF_R(29) TF_R(16) TF_R(24)  x0 += ks2; x1 += ks0 + 2u;
    TF_R(13) TF_R(15) TF_R(26) TF_R(6)   x0 += ks0; x1 += ks1 + 3u;
    TF_R(17) TF_R(29) TF_R(16) TF_R(24)  x0 += ks1; x1 += ks2 + 4u;
    TF_R(13) TF_R(15) TF_R(26) TF_R(6)   x0 += ks2; x1 += ks0 + 5u;
#undef TF_R
    return x0 ^ x1;
}
__device__ __forceinline__ float gumbel_from_bits(uint32_t bits) {
    float f = __uint_as_float((bits >> 9) | 0x3F800000u) - 1.0f;
    const float lo = 1e-6f;
    const float hi = (float)(1.0 - 1e-6);
    float u = fmaxf(lo, __fadd_rn(__fmul_rn(f, __fsub_rn(hi, lo)), lo));
    return -logf(-logf(u));
}

__global__ __launch_bounds__(256) void epilogue_kernel(
    const float* __restrict__ bias, const int* __restrict__ kptr,
    float* __restrict__ mask_out, float* __restrict__ wout,
    float* __restrict__ logits_out)
{
    __shared__ float ss[8][64];
    const int w    = threadIdx.x >> 5;
    const int lane = threadIdx.x & 31;
    const int row  = blockIdx.x * 8 + w;
    const int k    = *kptr;
    const int e0 = lane, e1 = lane + 32;
    const size_t base = (size_t)row * E_DIM;

    float l0 = ((g_partial[0][base + e0] + g_partial[1][base + e0])
              + (g_partial[2][base + e0] + g_partial[3][base + e0])) + bias[e0];
    float l1 = ((g_partial[0][base + e1] + g_partial[1][base + e1])
              + (g_partial[2][base + e1] + g_partial[3][base + e1])) + bias[e1];
    logits_out[base + e0] = l0;
    logits_out[base + e1] = l1;

    uint32_t i0 = (uint32_t)(row * E_DIM + e0);
    float s0 = l0 + gumbel_from_bits(threefry_xor_42(i0));
    float s1 = l1 + gumbel_from_bits(threefry_xor_42(i0 + 32u));

    float m = fmaxf(l0, l1);
#pragma unroll
    for (int off = 16; off; off >>= 1)
        m = fmaxf(m, __shfl_xor_sync(0xffffffffu, m, off));
    float p0 = expf(l0 - m), p1 = expf(l1 - m);
    float sum = p0 + p1;
#pragma unroll
    for (int off = 16; off; off >>= 1)
        sum += __shfl_xor_sync(0xffffffffu, sum, off);

    ss[w][e0] = s0;
    ss[w][e1] = s1;
    __syncwarp();
    int c0 = 0, c1 = 0;
#pragma unroll
    for (int jj = 0; jj < 64; jj++) {
        float v = ss[w][jj];
        c0 += (v > s0) || ((v == s0) && (jj < e0));
        c1 += (v > s1) || ((v == s1) && (jj < e1));
    }

    mask_out[base + e0] = (c0 < k) ? 1.0f : 0.0f;
    mask_out[base + e1] = (c1 < k) ? 1.0f : 0.0f;
    wout[base + e0] = p0 / sum;
    wout[base + e1] = p1 / sum;
}

// ===========================================================================
// Launch. Inputs matched by element count (h=33.5M, W=262144, bias=64, k=1).
// out = [mask | weight | logits], each T*E float32.
// ===========================================================================
extern "C" void kernel_launch(void* const* d_in, const int* in_sizes, int n_in,
                              void* d_out, int out_size) {
    const float* H    = nullptr;
    const float* Wm   = nullptr;
    const float* bias = nullptr;
    const int*   kptr = nullptr;
    for (int i = 0; i < n_in; i++) {
        long long sz = in_sizes[i];
        if (sz == (long long)T_DIM * D_DIM)      H    = (const float*)d_in[i];
        else if (sz == (long long)E_DIM * D_DIM) Wm   = (const float*)d_in[i];
        else if (sz == E_DIM)                    bias = (const float*)d_in[i];
        else if (sz == 1)                        kptr = (const int*)d_in[i];
    }
    if (!H)    H    = (const float*)d_in[0];
    if (!Wm)   Wm   = (const float*)d_in[1];
    if (!bias) bias = (const float*)d_in[2];
    if (!kptr) kptr = (const int*)d_in[3];

    float* out        = (float*)d_out;
    float* mask_out   = out;
    float* weight_out = out + (size_t)T_DIM * E_DIM;
    float* logits_out = out + 2 * (size_t)T_DIM * E_DIM;

    cudaFuncSetAttribute(gemm_kernel,
                         cudaFuncAttributeMaxDynamicSharedMemorySize, SMEM_BYTES);
    gemm_kernel<<<(T_DIM / 256) * KSPLIT, 512, SMEM_BYTES>>>(H, Wm);
    epilogue_kernel<<<T_DIM / 8, 256>>>(bias, kptr, mask_out, weight_out, logits_out);
}